// round 11
// baseline (speedup 1.0000x reference)
#include <cuda_runtime.h>
#include <math.h>

#define KC 8
#define GRID 296
#define NTHREADS 128

__device__ double g_part[GRID];
__device__ unsigned int g_ctr;   // zero-init; finalizer resets to 0 each run

__device__ __forceinline__ float ex2f(float x) {
    float r; asm("ex2.approx.f32 %0, %1;" : "=f"(r) : "f"(x)); return r;
}

// density + W-quadratic for one point — pure scalar fp32
__device__ __forceinline__ float point_num(
    float4 x, const float A[KC][10], const float B[KC][4],
    const float C2[KC], const float WP[36])
{
    float d[KC];
#pragma unroll
    for (int k = 0; k < KC; k++) {
        float y0 = fmaf(A[k][0], x.x, B[k][0]);
        float y1 = fmaf(A[k][1], x.x, fmaf(A[k][2], x.y, B[k][1]));
        float y2 = fmaf(A[k][3], x.x, fmaf(A[k][4], x.y, fmaf(A[k][5], x.z, B[k][2])));
        float y3 = fmaf(A[k][6], x.x, fmaf(A[k][7], x.y, fmaf(A[k][8], x.z, fmaf(A[k][9], x.w, B[k][3]))));
        float tq = C2[k];
        tq = fmaf(-y0, y0, tq);
        tq = fmaf(-y1, y1, tq);
        tq = fmaf(-y2, y2, tq);
        tq = fmaf(-y3, y3, tq);
        d[k] = ex2f(tq);
    }
    // num = d^T W d, symmetric packing; two accumulators shorten the tail chain
    float numA = 0.0f, numB = 0.0f;
    int idx = 0;
#pragma unroll
    for (int a = 0; a < KC; a++) {
        float h = WP[idx++] * d[a];
#pragma unroll
        for (int b = a + 1; b < KC; b++) h = fmaf(WP[idx++], d[b], h);
        if (a & 1) numB = fmaf(d[a], h, numB);
        else       numA = fmaf(d[a], h, numA);
    }
    return numA + numB;
}

// =======================================================================
// ONE fused kernel: per-block redundant setup -> main loop (4-pt unroll,
// software-pipelined loads, pure scalar math) -> last-block finalize.
// =======================================================================
__global__ void __launch_bounds__(NTHREADS) gmm_all(
    const float4* __restrict__ X,
    const float*  __restrict__ means,
    const float*  __restrict__ chols,
    const float*  __restrict__ weights,
    float* __restrict__ out, int N)
{
    __shared__ float sA[KC][10];
    __shared__ float sB[KC][4];
    __shared__ float sC2[KC];
    __shared__ float sW[KC][KC];
    __shared__ float sSig[KC][16];
    __shared__ float red0[2], red1[2], red2[2];
    __shared__ float slogz;
    __shared__ double sred[NTHREADS / 32];
    __shared__ int s_last;

    const int t = threadIdx.x;
    const int lane = t & 31, warp = t >> 5;
    const unsigned full = 0xffffffffu;
    const float LOG2E = 1.4426950408889634f;
    const float LN2PI = 1.8378770664093454f;
    const float SCL   = 0.8493218002880191f;   // sqrt(0.5*log2(e))

    // ---------------- setup phase 1: per-cluster constants (threads 0..7) ----
    if (t < KC) {
        const int k = t;
        float L[4][4];
#pragma unroll
        for (int r = 0; r < 4; r++)
#pragma unroll
            for (int c = 0; c < 4; c++)
                L[r][c] = (c <= r) ? chols[k * 16 + r * 4 + c] : 0.0f;
        float S[4][4];
#pragma unroll
        for (int r = 0; r < 4; r++)
#pragma unroll
            for (int c = 0; c < 4; c++) {
                float s = (r == c) ? 1.0f : 0.0f;
#pragma unroll
                for (int m = 0; m < 4; m++) s = fmaf(L[r][m], L[c][m], s);
                S[r][c] = s;
                sSig[k][r * 4 + c] = s;
            }
        float M[4][4];
#pragma unroll
        for (int r = 0; r < 4; r++) {
#pragma unroll
            for (int c = 0; c < 4; c++) {
                if (c > r) { M[r][c] = 0.0f; continue; }
                float s = S[r][c];
#pragma unroll
                for (int m = 0; m < 4; m++)
                    if (m < c) s = fmaf(-M[r][m], M[c][m], s);
                if (r == c) M[r][r] = sqrtf(s);
                else        M[r][c] = s / M[c][c];
            }
        }
        float A[4][4];
#pragma unroll
        for (int r = 0; r < 4; r++) {
#pragma unroll
            for (int c = 0; c < 4; c++) A[r][c] = 0.0f;
            A[r][r] = 1.0f / M[r][r];
#pragma unroll
            for (int c = 0; c < 4; c++) {
                if (c >= r) continue;
                float s = 0.0f;
#pragma unroll
                for (int m = 0; m < 4; m++)
                    if (m >= c && m < r) s = fmaf(M[r][m], A[m][c], s);
                A[r][c] = -s * A[r][r];
            }
        }
        float logdet = 2.0f * logf(M[0][0] * M[1][1] * M[2][2] * M[3][3]);
        sC2[k] = -0.5f * (4.0f * LN2PI + logdet) * LOG2E;
        int idx = 0;
#pragma unroll
        for (int r = 0; r < 4; r++)
#pragma unroll
            for (int c = 0; c < 4; c++)
                if (c <= r) sA[k][idx++] = A[r][c] * SCL;
#pragma unroll
        for (int r = 0; r < 4; r++) {
            float b = 0.0f;
#pragma unroll
            for (int c = 0; c < 4; c++)
                if (c <= r) b = fmaf(A[r][c], means[k * 4 + c], b);
            sB[k][r] = -b * SCL;
        }
    }
    __syncthreads();

    // ---------------- setup phase 2: softmax W + z (threads 0..63) ----------
    const int i8 = t >> 3, j8 = t & 7;
    float wij = 0.0f, m = -1e30f;
    if (t < 64) {
        wij = weights[i8] * weights[j8];
        m = wij;
#pragma unroll
        for (int o = 16; o > 0; o >>= 1) m = fmaxf(m, __shfl_xor_sync(full, m, o));
        if (lane == 0) red0[warp] = m;
    }
    __syncthreads();
    float e = 0.0f;
    if (t < 64) {
        m = fmaxf(red0[0], red0[1]);
        e = __expf(wij - m);
        float s = e;
#pragma unroll
        for (int o = 16; o > 0; o >>= 1) s += __shfl_xor_sync(full, s, o);
        if (lane == 0) red1[warp] = s;
    }
    __syncthreads();
    if (t < 64) {
        float s = red1[0] + red1[1];
        float Wij = e / s;
        sW[i8][j8] = Wij;
        float Ss[4][4];
#pragma unroll
        for (int r = 0; r < 4; r++)
#pragma unroll
            for (int c = 0; c < 4; c++)
                Ss[r][c] = sSig[i8][r * 4 + c] + sSig[j8][r * 4 + c];
        float M[4][4];
#pragma unroll
        for (int r = 0; r < 4; r++) {
#pragma unroll
            for (int c = 0; c < 4; c++) {
                if (c > r) { M[r][c] = 0.0f; continue; }
                float s2 = Ss[r][c];
#pragma unroll
                for (int mm = 0; mm < 4; mm++)
                    if (mm < c) s2 = fmaf(-M[r][mm], M[c][mm], s2);
                if (r == c) M[r][r] = sqrtf(s2);
                else        M[r][c] = s2 / M[c][c];
            }
        }
        float ld = 2.0f * logf(M[0][0] * M[1][1] * M[2][2] * M[3][3]);
        float y[4];
#pragma unroll
        for (int r = 0; r < 4; r++) {
            float s2 = means[i8 * 4 + r] - means[j8 * 4 + r];
#pragma unroll
            for (int mm = 0; mm < 4; mm++)
                if (mm < r) s2 = fmaf(-M[r][mm], y[mm], s2);
            y[r] = s2 / M[r][r];
        }
        float md = y[0] * y[0] + y[1] * y[1] + y[2] * y[2] + y[3] * y[3];
        float zc = Wij * __expf(-0.5f * md - 0.5f * (4.0f * LN2PI + ld));
#pragma unroll
        for (int o = 16; o > 0; o >>= 1) zc += __shfl_xor_sync(full, zc, o);
        if (lane == 0) red2[warp] = zc;
    }
    __syncthreads();
    if (t == 0) slogz = logf(red2[0] + red2[1]);
    __syncthreads();

    // ---------------- load constants into registers (scalar) -----------------
    float A[KC][10], B[KC][4], C2[KC], WP[36];
#pragma unroll
    for (int k = 0; k < KC; k++) {
#pragma unroll
        for (int q = 0; q < 10; q++) A[k][q] = sA[k][q];
#pragma unroll
        for (int q = 0; q < 4; q++)  B[k][q] = sB[k][q];
        C2[k] = sC2[k];
    }
    {
        int idx = 0;
#pragma unroll
        for (int a = 0; a < KC; a++) {
            WP[idx++] = sW[a][a];
#pragma unroll
            for (int b = a + 1; b < KC; b++) WP[idx++] = 2.0f * sW[a][b];
        }
    }

    // ---------------- main loop: 4 points, software-pipelined loads ----------
    double acc = 0.0;
    const int gid = blockIdx.x * blockDim.x + t;
    const int nthr = gridDim.x * blockDim.x;
    const int step = 4 * nthr;
    int i = 4 * gid;

    float4 xa, xb, xc, xd;
    bool have = (i + 3 < N);
    if (have) {
        xa = X[i]; xb = X[i + 1]; xc = X[i + 2]; xd = X[i + 3];
    }
    while (have) {
        const int inext = i + step;
        const bool havenext = (inext + 3 < N);
        float4 ya, yb, yc, yd;
        if (havenext) {            // prefetch next group BEFORE computing
            ya = X[inext]; yb = X[inext + 1]; yc = X[inext + 2]; yd = X[inext + 3];
        }
        float n0 = point_num(xa, A, B, C2, WP);
        float n1 = point_num(xb, A, B, C2, WP);
        float n2 = point_num(xc, A, B, C2, WP);
        float n3 = point_num(xd, A, B, C2, WP);
        acc += (double)((n0 + n1) + (n2 + n3));
        xa = ya; xb = yb; xc = yc; xd = yd;
        i = inext;
        have = havenext;
    }
    // tail: at most the one straddling group
    for (; i < N; i++)
        acc += (double)point_num(X[i], A, B, C2, WP);

    // ---------------- block reduction (double) -------------------------------
#pragma unroll
    for (int o = 16; o > 0; o >>= 1) acc += __shfl_down_sync(full, acc, o);
    if (lane == 0) sred[warp] = acc;
    __syncthreads();
    if (t == 0) {
        double v = 0.0;
#pragma unroll
        for (int w2 = 0; w2 < NTHREADS / 32; w2++) v += sred[w2];
        g_part[blockIdx.x] = v;
        __threadfence();
        unsigned old = atomicAdd(&g_ctr, 1u);
        s_last = (old == gridDim.x - 1) ? 1 : 0;
    }
    __syncthreads();

    // ---------------- last block finalizes -----------------------------------
    if (s_last && warp == 0) {
        double s = 0.0;
        for (int b = lane; b < GRID; b += 32) s += g_part[b];
#pragma unroll
        for (int o = 16; o > 0; o >>= 1) s += __shfl_down_sync(full, s, o);
        if (lane == 0) {
            out[0] = (float)(-(log(s) - (double)slogz) / (double)N);
            g_ctr = 0;   // reset for next graph replay
        }
    }
}

extern "C" void kernel_launch(void* const* d_in, const int* in_sizes, int n_in,
                              void* d_out, int out_size) {
    const float* X       = (const float*)d_in[0];
    const float* means   = (const float*)d_in[1];
    const float* chols   = (const float*)d_in[2];
    const float* weights = (const float*)d_in[3];
    const int N = in_sizes[0] / 4;
    float* out = (float*)d_out;

    gmm_all<<<GRID, NTHREADS>>>((const float4*)X, means, chols, weights, out, N);
}

// round 12
// speedup vs baseline: 1.0707x; 1.0707x over previous
#include <cuda_runtime.h>
#include <math.h>

#define KC 8
#define GRID 296
#define NTHREADS 128

typedef unsigned long long ull;

__device__ double g_part[GRID];
__device__ unsigned int g_ctr;   // zero-init; finalizer resets to 0 each run

// ---- packed f32x2 helpers ----
__device__ __forceinline__ ull f2fma(ull a, ull b, ull c) {
    ull r; asm("fma.rn.f32x2 %0, %1, %2, %3;" : "=l"(r) : "l"(a), "l"(b), "l"(c)); return r;
}
__device__ __forceinline__ ull f2mul(ull a, ull b) {
    ull r; asm("mul.rn.f32x2 %0, %1, %2;" : "=l"(r) : "l"(a), "l"(b)); return r;
}
__device__ __forceinline__ ull pk2(float lo, float hi) {
    ull r; asm("mov.b64 %0, {%1, %2};" : "=l"(r) : "f"(lo), "f"(hi)); return r;
}
__device__ __forceinline__ void upk2(ull v, float& lo, float& hi) {
    asm("mov.b64 {%0, %1}, %2;" : "=f"(lo), "=f"(hi) : "l"(v));
}
__device__ __forceinline__ float ex2f(float x) {
    float r; asm("ex2.approx.f32 %0, %1;" : "=f"(r) : "f"(x)); return r;
}

// density + W-quadratic for one point (cluster-paired density, scalar quad)
__device__ __forceinline__ float point_num(
    float4 x, const ull PA[4][10], const ull PB[4][4], const ull PC2[4],
    const float WP[36])
{
    ull Xx = pk2(x.x, x.x), Xy = pk2(x.y, x.y), Xz = pk2(x.z, x.z), Xw = pk2(x.w, x.w);
    const ull NEG1 = pk2(-1.0f, -1.0f);
    float d[KC];
#pragma unroll
    for (int p = 0; p < 4; p++) {
        ull y0 = f2fma(PA[p][0], Xx, PB[p][0]);
        ull y1 = f2fma(PA[p][1], Xx, f2fma(PA[p][2], Xy, PB[p][1]));
        ull y2 = f2fma(PA[p][3], Xx, f2fma(PA[p][4], Xy, f2fma(PA[p][5], Xz, PB[p][2])));
        ull y3 = f2fma(PA[p][6], Xx, f2fma(PA[p][7], Xy, f2fma(PA[p][8], Xz, f2fma(PA[p][9], Xw, PB[p][3]))));
        ull s = f2mul(y0, y0);
        s = f2fma(y1, y1, s);
        s = f2fma(y2, y2, s);
        s = f2fma(y3, y3, s);
        ull tq = f2fma(s, NEG1, PC2[p]);   // C2 - s, packed
        float t0, t1;
        upk2(tq, t0, t1);
        d[2 * p]     = ex2f(t0);
        d[2 * p + 1] = ex2f(t1);
    }
    float num = 0.0f;
    int idx = 0;
#pragma unroll
    for (int a = 0; a < KC; a++) {
        float h = WP[idx++] * d[a];
#pragma unroll
        for (int b = a + 1; b < KC; b++) h = fmaf(WP[idx++], d[b], h);
        num = fmaf(d[a], h, num);
    }
    return num;
}

// =======================================================================
// ONE fused kernel: per-block redundant setup -> main loop (4-pt unroll,
// software-pipelined streaming loads, uniform trip count) -> tail ->
// last-block finalize.
// =======================================================================
__global__ void __launch_bounds__(NTHREADS) gmm_all(
    const float4* __restrict__ X,
    const float*  __restrict__ means,
    const float*  __restrict__ chols,
    const float*  __restrict__ weights,
    float* __restrict__ out, int N)
{
    __shared__ float sA[KC][10];
    __shared__ float sB[KC][4];
    __shared__ float sC2[KC];
    __shared__ float sW[KC][KC];
    __shared__ float sSig[KC][16];
    __shared__ float red0[2], red1[2], red2[2];
    __shared__ float slogz;
    __shared__ double sred[NTHREADS / 32];
    __shared__ int s_last;

    const int t = threadIdx.x;
    const int lane = t & 31, warp = t >> 5;
    const unsigned full = 0xffffffffu;
    const float LOG2E = 1.4426950408889634f;
    const float LN2PI = 1.8378770664093454f;
    const float SCL   = 0.8493218002880191f;   // sqrt(0.5*log2(e))

    // ---------------- setup phase 1: per-cluster constants (threads 0..7) ----
    if (t < KC) {
        const int k = t;
        float L[4][4];
#pragma unroll
        for (int r = 0; r < 4; r++)
#pragma unroll
            for (int c = 0; c < 4; c++)
                L[r][c] = (c <= r) ? chols[k * 16 + r * 4 + c] : 0.0f;
        float S[4][4];
#pragma unroll
        for (int r = 0; r < 4; r++)
#pragma unroll
            for (int c = 0; c < 4; c++) {
                float s = (r == c) ? 1.0f : 0.0f;
#pragma unroll
                for (int m = 0; m < 4; m++) s = fmaf(L[r][m], L[c][m], s);
                S[r][c] = s;
                sSig[k][r * 4 + c] = s;
            }
        float M[4][4];
#pragma unroll
        for (int r = 0; r < 4; r++) {
#pragma unroll
            for (int c = 0; c < 4; c++) {
                if (c > r) { M[r][c] = 0.0f; continue; }
                float s = S[r][c];
#pragma unroll
                for (int m = 0; m < 4; m++)
                    if (m < c) s = fmaf(-M[r][m], M[c][m], s);
                if (r == c) M[r][r] = sqrtf(s);
                else        M[r][c] = s / M[c][c];
            }
        }
        float A[4][4];
#pragma unroll
        for (int r = 0; r < 4; r++) {
#pragma unroll
            for (int c = 0; c < 4; c++) A[r][c] = 0.0f;
            A[r][r] = 1.0f / M[r][r];
#pragma unroll
            for (int c = 0; c < 4; c++) {
                if (c >= r) continue;
                float s = 0.0f;
#pragma unroll
                for (int m = 0; m < 4; m++)
                    if (m >= c && m < r) s = fmaf(M[r][m], A[m][c], s);
                A[r][c] = -s * A[r][r];
            }
        }
        float logdet = 2.0f * logf(M[0][0] * M[1][1] * M[2][2] * M[3][3]);
        sC2[k] = -0.5f * (4.0f * LN2PI + logdet) * LOG2E;
        int idx = 0;
#pragma unroll
        for (int r = 0; r < 4; r++)
#pragma unroll
            for (int c = 0; c < 4; c++)
                if (c <= r) sA[k][idx++] = A[r][c] * SCL;
#pragma unroll
        for (int r = 0; r < 4; r++) {
            float b = 0.0f;
#pragma unroll
            for (int c = 0; c < 4; c++)
                if (c <= r) b = fmaf(A[r][c], means[k * 4 + c], b);
            sB[k][r] = -b * SCL;
        }
    }
    __syncthreads();

    // ---------------- setup phase 2: softmax W + z (threads 0..63) ----------
    const int i8 = t >> 3, j8 = t & 7;
    float wij = 0.0f, m = -1e30f;
    if (t < 64) {
        wij = weights[i8] * weights[j8];
        m = wij;
#pragma unroll
        for (int o = 16; o > 0; o >>= 1) m = fmaxf(m, __shfl_xor_sync(full, m, o));
        if (lane == 0) red0[warp] = m;
    }
    __syncthreads();
    float e = 0.0f;
    if (t < 64) {
        m = fmaxf(red0[0], red0[1]);
        e = __expf(wij - m);
        float s = e;
#pragma unroll
        for (int o = 16; o > 0; o >>= 1) s += __shfl_xor_sync(full, s, o);
        if (lane == 0) red1[warp] = s;
    }
    __syncthreads();
    if (t < 64) {
        float s = red1[0] + red1[1];
        float Wij = e / s;
        sW[i8][j8] = Wij;
        float Ss[4][4];
#pragma unroll
        for (int r = 0; r < 4; r++)
#pragma unroll
            for (int c = 0; c < 4; c++)
                Ss[r][c] = sSig[i8][r * 4 + c] + sSig[j8][r * 4 + c];
        float M[4][4];
#pragma unroll
        for (int r = 0; r < 4; r++) {
#pragma unroll
            for (int c = 0; c < 4; c++) {
                if (c > r) { M[r][c] = 0.0f; continue; }
                float s2 = Ss[r][c];
#pragma unroll
                for (int mm = 0; mm < 4; mm++)
                    if (mm < c) s2 = fmaf(-M[r][mm], M[c][mm], s2);
                if (r == c) M[r][r] = sqrtf(s2);
                else        M[r][c] = s2 / M[c][c];
            }
        }
        float ld = 2.0f * logf(M[0][0] * M[1][1] * M[2][2] * M[3][3]);
        float y[4];
#pragma unroll
        for (int r = 0; r < 4; r++) {
            float s2 = means[i8 * 4 + r] - means[j8 * 4 + r];
#pragma unroll
            for (int mm = 0; mm < 4; mm++)
                if (mm < r) s2 = fmaf(-M[r][mm], y[mm], s2);
            y[r] = s2 / M[r][r];
        }
        float md = y[0] * y[0] + y[1] * y[1] + y[2] * y[2] + y[3] * y[3];
        float zc = Wij * __expf(-0.5f * md - 0.5f * (4.0f * LN2PI + ld));
#pragma unroll
        for (int o = 16; o > 0; o >>= 1) zc += __shfl_xor_sync(full, zc, o);
        if (lane == 0) red2[warp] = zc;
    }
    __syncthreads();
    if (t == 0) slogz = logf(red2[0] + red2[1]);
    __syncthreads();

    // ---------------- load + pack constants into registers -------------------
    ull PA[4][10], PB[4][4], PC2[4];
    float WP[36];
#pragma unroll
    for (int p = 0; p < 4; p++) {
#pragma unroll
        for (int q = 0; q < 10; q++) PA[p][q] = pk2(sA[2 * p][q], sA[2 * p + 1][q]);
#pragma unroll
        for (int q = 0; q < 4; q++)  PB[p][q] = pk2(sB[2 * p][q], sB[2 * p + 1][q]);
        PC2[p] = pk2(sC2[2 * p], sC2[2 * p + 1]);
    }
    {
        int idx = 0;
#pragma unroll
        for (int a = 0; a < KC; a++) {
            WP[idx++] = sW[a][a];
#pragma unroll
            for (int b = a + 1; b < KC; b++) WP[idx++] = 2.0f * sW[a][b];
        }
    }

    // ---------------- main loop: uniform trip count, pipelined ---------------
    // Every thread runs exactly Kiter 4-pt groups (perfect balance), then the
    // remainder (< nthr points) is distributed 1 point/thread.
    double acc = 0.0;
    const int gid = blockIdx.x * blockDim.x + t;
    const int nthr = gridDim.x * blockDim.x;
    const int step = 4 * nthr;
    const int Kiter = N / step;                 // full rounds for ALL threads
    int i = 4 * gid;

    if (Kiter > 0) {
        float4 xa = __ldcs(&X[i]);
        float4 xb = __ldcs(&X[i + 1]);
        float4 xc = __ldcs(&X[i + 2]);
        float4 xd = __ldcs(&X[i + 3]);
        for (int r = 0; r < Kiter; r++) {
            const int inext = i + step;
            float4 ya, yb, yc, yd;
            if (r + 1 < Kiter) {       // prefetch next group BEFORE computing
                ya = __ldcs(&X[inext]);
                yb = __ldcs(&X[inext + 1]);
                yc = __ldcs(&X[inext + 2]);
                yd = __ldcs(&X[inext + 3]);
            }
            float n0 = point_num(xa, PA, PB, PC2, WP);
            float n1 = point_num(xb, PA, PB, PC2, WP);
            float n2 = point_num(xc, PA, PB, PC2, WP);
            float n3 = point_num(xd, PA, PB, PC2, WP);
            acc += (double)((n0 + n1) + (n2 + n3));
            xa = ya; xb = yb; xc = yc; xd = yd;
            i = inext;
        }
    }
    // tail: N - Kiter*step points, strided 1/thread (at most 1 each here,
    // loop kept general for safety)
    for (int j = Kiter * step + gid; j < N; j += nthr)
        acc += (double)point_num(__ldcs(&X[j]), PA, PB, PC2, WP);

    // ---------------- block reduction (double) -------------------------------
#pragma unroll
    for (int o = 16; o > 0; o >>= 1) acc += __shfl_down_sync(full, acc, o);
    if (lane == 0) sred[warp] = acc;
    __syncthreads();
    if (t == 0) {
        double v = 0.0;
#pragma unroll
        for (int w2 = 0; w2 < NTHREADS / 32; w2++) v += sred[w2];
        g_part[blockIdx.x] = v;
        __threadfence();
        unsigned old = atomicAdd(&g_ctr, 1u);
        s_last = (old == gridDim.x - 1) ? 1 : 0;
    }
    __syncthreads();

    // ---------------- last block finalizes -----------------------------------
    if (s_last && warp == 0) {
        double s = 0.0;
        for (int b = lane; b < GRID; b += 32) s += g_part[b];
#pragma unroll
        for (int o = 16; o > 0; o >>= 1) s += __shfl_down_sync(full, s, o);
        if (lane == 0) {
            out[0] = (float)(-(log(s) - (double)slogz) / (double)N);
            g_ctr = 0;   // reset for next graph replay
        }
    }
}

extern "C" void kernel_launch(void* const* d_in, const int* in_sizes, int n_in,
                              void* d_out, int out_size) {
    const float* X       = (const float*)d_in[0];
    const float* means   = (const float*)d_in[1];
    const float* chols   = (const float*)d_in[2];
    const float* weights = (const float*)d_in[3];
    const int N = in_sizes[0] / 4;
    float* out = (float*)d_out;

    gmm_all<<<GRID, NTHREADS>>>((const float4*)X, means, chols, weights, out, N);
}

// round 13
// speedup vs baseline: 1.0801x; 1.0088x over previous
#include <cuda_runtime.h>
#include <math.h>

#define KC 8
#define GRID 296
#define NTHREADS 128

typedef unsigned long long ull;

__device__ double g_part[GRID];
__device__ unsigned int g_ctr;   // zero-init; finalizer resets to 0 each run

// ---- packed f32x2 helpers ----
__device__ __forceinline__ ull f2fma(ull a, ull b, ull c) {
    ull r; asm("fma.rn.f32x2 %0, %1, %2, %3;" : "=l"(r) : "l"(a), "l"(b), "l"(c)); return r;
}
__device__ __forceinline__ ull f2mul(ull a, ull b) {
    ull r; asm("mul.rn.f32x2 %0, %1, %2;" : "=l"(r) : "l"(a), "l"(b)); return r;
}
__device__ __forceinline__ ull pk2(float lo, float hi) {
    ull r; asm("mov.b64 %0, {%1, %2};" : "=l"(r) : "f"(lo), "f"(hi)); return r;
}
__device__ __forceinline__ void upk2(ull v, float& lo, float& hi) {
    asm("mov.b64 {%0, %1}, %2;" : "=f"(lo), "=f"(hi) : "l"(v));
}
__device__ __forceinline__ float ex2f(float x) {
    float r; asm("ex2.approx.f32 %0, %1;" : "=f"(r) : "f"(x)); return r;
}
// shared load that ptxas cannot hoist into long-lived registers
__device__ __forceinline__ ull lds64(unsigned addr) {
    ull r; asm volatile("ld.shared.b64 %0, [%1];" : "=l"(r) : "r"(addr)); return r;
}

// densities for one point, cluster-paired constants (register-resident)
__device__ __forceinline__ void point_dens(
    float4 x, const ull PA[4][10], const ull PB[4][4], const ull PC2[4],
    float d[KC])
{
    ull Xx = pk2(x.x, x.x), Xy = pk2(x.y, x.y), Xz = pk2(x.z, x.z), Xw = pk2(x.w, x.w);
    const ull NEG1 = pk2(-1.0f, -1.0f);
#pragma unroll
    for (int p = 0; p < 4; p++) {
        ull y0 = f2fma(PA[p][0], Xx, PB[p][0]);
        ull y1 = f2fma(PA[p][1], Xx, f2fma(PA[p][2], Xy, PB[p][1]));
        ull y2 = f2fma(PA[p][3], Xx, f2fma(PA[p][4], Xy, f2fma(PA[p][5], Xz, PB[p][2])));
        ull y3 = f2fma(PA[p][6], Xx, f2fma(PA[p][7], Xy, f2fma(PA[p][8], Xz, f2fma(PA[p][9], Xw, PB[p][3]))));
        ull s = f2mul(y0, y0);
        s = f2fma(y1, y1, s);
        s = f2fma(y2, y2, s);
        s = f2fma(y3, y3, s);
        ull tq = f2fma(s, NEG1, PC2[p]);   // C2 - s, packed
        float t0, t1;
        upk2(tq, t0, t1);
        d[2 * p]     = ex2f(t0);
        d[2 * p + 1] = ex2f(t1);
    }
}

// =======================================================================
// ONE fused kernel: per-block redundant setup -> main loop (4-pt unroll,
// pipelined loads, point-packed quad with W streamed from SMEM) ->
// last-block finalize.
// =======================================================================
__global__ void __launch_bounds__(NTHREADS) gmm_all(
    const float4* __restrict__ X,
    const float*  __restrict__ means,
    const float*  __restrict__ chols,
    const float*  __restrict__ weights,
    float* __restrict__ out, int N)
{
    __shared__ float sA[KC][10];
    __shared__ float sB[KC][4];
    __shared__ float sC2[KC];
    __shared__ float sW[KC][KC];
    __shared__ ull  sWPu[36];        // packed (w,w) symmetric weights
    __shared__ float sSig[KC][16];
    __shared__ float red0[2], red1[2], red2[2];
    __shared__ float slogz;
    __shared__ double sred[NTHREADS / 32];
    __shared__ int s_last;

    const int t = threadIdx.x;
    const int lane = t & 31, warp = t >> 5;
    const unsigned full = 0xffffffffu;
    const float LOG2E = 1.4426950408889634f;
    const float LN2PI = 1.8378770664093454f;
    const float SCL   = 0.8493218002880191f;   // sqrt(0.5*log2(e))

    // ---------------- setup phase 1: per-cluster constants (threads 0..7) ----
    if (t < KC) {
        const int k = t;
        float L[4][4];
#pragma unroll
        for (int r = 0; r < 4; r++)
#pragma unroll
            for (int c = 0; c < 4; c++)
                L[r][c] = (c <= r) ? chols[k * 16 + r * 4 + c] : 0.0f;
        float S[4][4];
#pragma unroll
        for (int r = 0; r < 4; r++)
#pragma unroll
            for (int c = 0; c < 4; c++) {
                float s = (r == c) ? 1.0f : 0.0f;
#pragma unroll
                for (int m = 0; m < 4; m++) s = fmaf(L[r][m], L[c][m], s);
                S[r][c] = s;
                sSig[k][r * 4 + c] = s;
            }
        float M[4][4];
#pragma unroll
        for (int r = 0; r < 4; r++) {
#pragma unroll
            for (int c = 0; c < 4; c++) {
                if (c > r) { M[r][c] = 0.0f; continue; }
                float s = S[r][c];
#pragma unroll
                for (int m = 0; m < 4; m++)
                    if (m < c) s = fmaf(-M[r][m], M[c][m], s);
                if (r == c) M[r][r] = sqrtf(s);
                else        M[r][c] = s / M[c][c];
            }
        }
        float A[4][4];
#pragma unroll
        for (int r = 0; r < 4; r++) {
#pragma unroll
            for (int c = 0; c < 4; c++) A[r][c] = 0.0f;
            A[r][r] = 1.0f / M[r][r];
#pragma unroll
            for (int c = 0; c < 4; c++) {
                if (c >= r) continue;
                float s = 0.0f;
#pragma unroll
                for (int m = 0; m < 4; m++)
                    if (m >= c && m < r) s = fmaf(M[r][m], A[m][c], s);
                A[r][c] = -s * A[r][r];
            }
        }
        float logdet = 2.0f * logf(M[0][0] * M[1][1] * M[2][2] * M[3][3]);
        sC2[k] = -0.5f * (4.0f * LN2PI + logdet) * LOG2E;
        int idx = 0;
#pragma unroll
        for (int r = 0; r < 4; r++)
#pragma unroll
            for (int c = 0; c < 4; c++)
                if (c <= r) sA[k][idx++] = A[r][c] * SCL;
#pragma unroll
        for (int r = 0; r < 4; r++) {
            float b = 0.0f;
#pragma unroll
            for (int c = 0; c < 4; c++)
                if (c <= r) b = fmaf(A[r][c], means[k * 4 + c], b);
            sB[k][r] = -b * SCL;
        }
    }
    __syncthreads();

    // ---------------- setup phase 2: softmax W + z (threads 0..63) ----------
    const int i8 = t >> 3, j8 = t & 7;
    float wij = 0.0f, m = -1e30f;
    if (t < 64) {
        wij = weights[i8] * weights[j8];
        m = wij;
#pragma unroll
        for (int o = 16; o > 0; o >>= 1) m = fmaxf(m, __shfl_xor_sync(full, m, o));
        if (lane == 0) red0[warp] = m;
    }
    __syncthreads();
    float e = 0.0f;
    if (t < 64) {
        m = fmaxf(red0[0], red0[1]);
        e = __expf(wij - m);
        float s = e;
#pragma unroll
        for (int o = 16; o > 0; o >>= 1) s += __shfl_xor_sync(full, s, o);
        if (lane == 0) red1[warp] = s;
    }
    __syncthreads();
    if (t < 64) {
        float s = red1[0] + red1[1];
        float Wij = e / s;
        sW[i8][j8] = Wij;
        float Ss[4][4];
#pragma unroll
        for (int r = 0; r < 4; r++)
#pragma unroll
            for (int c = 0; c < 4; c++)
                Ss[r][c] = sSig[i8][r * 4 + c] + sSig[j8][r * 4 + c];
        float M[4][4];
#pragma unroll
        for (int r = 0; r < 4; r++) {
#pragma unroll
            for (int c = 0; c < 4; c++) {
                if (c > r) { M[r][c] = 0.0f; continue; }
                float s2 = Ss[r][c];
#pragma unroll
                for (int mm = 0; mm < 4; mm++)
                    if (mm < c) s2 = fmaf(-M[r][mm], M[c][mm], s2);
                if (r == c) M[r][r] = sqrtf(s2);
                else        M[r][c] = s2 / M[c][c];
            }
        }
        float ld = 2.0f * logf(M[0][0] * M[1][1] * M[2][2] * M[3][3]);
        float y[4];
#pragma unroll
        for (int r = 0; r < 4; r++) {
            float s2 = means[i8 * 4 + r] - means[j8 * 4 + r];
#pragma unroll
            for (int mm = 0; mm < 4; mm++)
                if (mm < r) s2 = fmaf(-M[r][mm], y[mm], s2);
            y[r] = s2 / M[r][r];
        }
        float md = y[0] * y[0] + y[1] * y[1] + y[2] * y[2] + y[3] * y[3];
        float zc = Wij * __expf(-0.5f * md - 0.5f * (4.0f * LN2PI + ld));
#pragma unroll
        for (int o = 16; o > 0; o >>= 1) zc += __shfl_xor_sync(full, zc, o);
        if (lane == 0) red2[warp] = zc;
    }
    __syncthreads();
    if (t == 0) {
        slogz = logf(red2[0] + red2[1]);
        int idx = 0;
#pragma unroll
        for (int a = 0; a < KC; a++) {
            float w0 = sW[a][a];
            sWPu[idx++] = pk2(w0, w0);
#pragma unroll
            for (int b = a + 1; b < KC; b++) {
                float w2 = 2.0f * sW[a][b];
                sWPu[idx++] = pk2(w2, w2);
            }
        }
    }
    __syncthreads();

    // ---------------- register constants: A/B/C2 -----------------------------
    ull PA[4][10], PB[4][4], PC2[4];
#pragma unroll
    for (int p = 0; p < 4; p++) {
#pragma unroll
        for (int q = 0; q < 10; q++) PA[p][q] = pk2(sA[2 * p][q], sA[2 * p + 1][q]);
#pragma unroll
        for (int q = 0; q < 4; q++)  PB[p][q] = pk2(sB[2 * p][q], sB[2 * p + 1][q]);
        PC2[p] = pk2(sC2[2 * p], sC2[2 * p + 1]);
    }
    const unsigned wbase = (unsigned)__cvta_generic_to_shared(sWPu);

    // ---------------- main loop: 4 points, pipelined, packed quad ------------
    double acc = 0.0;
    const int gid = blockIdx.x * blockDim.x + t;
    const int nthr = gridDim.x * blockDim.x;
    const int step = 4 * nthr;
    int i = 4 * gid;

    float4 xa, xb, xc, xd;
    bool have = (i + 3 < N);
    if (have) {
        xa = X[i]; xb = X[i + 1]; xc = X[i + 2]; xd = X[i + 3];
    }
    while (have) {
        const int inext = i + step;
        const bool havenext = (inext + 3 < N);
        float4 ya, yb, yc, yd;
        if (havenext) {            // prefetch next group BEFORE computing
            ya = X[inext]; yb = X[inext + 1]; yc = X[inext + 2]; yd = X[inext + 3];
        }
        float da[KC], db[KC], dc[KC], de[KC];
        point_dens(xa, PA, PB, PC2, da);
        point_dens(xb, PA, PB, PC2, db);
        point_dens(xc, PA, PB, PC2, dc);
        point_dens(xd, PA, PB, PC2, de);
        // point-packed W-quadratic: W streamed from SMEM, shared by both pairs
        ull dd01[KC], dd23[KC];
#pragma unroll
        for (int b = 0; b < KC; b++) {
            dd01[b] = pk2(da[b], db[b]);
            dd23[b] = pk2(dc[b], de[b]);
        }
        ull acc01 = 0ull, acc23 = 0ull;
        unsigned waddr = wbase;
#pragma unroll
        for (int a = 0; a < KC; a++) {
            ull w = lds64(waddr); waddr += 8;
            ull h01 = f2mul(w, dd01[a]);
            ull h23 = f2mul(w, dd23[a]);
#pragma unroll
            for (int b = a + 1; b < KC; b++) {
                w = lds64(waddr); waddr += 8;
                h01 = f2fma(w, dd01[b], h01);
                h23 = f2fma(w, dd23[b], h23);
            }
            acc01 = f2fma(dd01[a], h01, acc01);
            acc23 = f2fma(dd23[a], h23, acc23);
        }
        float n0, n1, n2, n3;
        upk2(acc01, n0, n1);
        upk2(acc23, n2, n3);
        acc += (double)((n0 + n1) + (n2 + n3));
        xa = ya; xb = yb; xc = yc; xd = yd;
        i = inext;
        have = havenext;
    }
    // tail: at most the one straddling group (packed quad on (d,d))
    for (; i < N; i++) {
        float dd[KC];
        point_dens(X[i], PA, PB, PC2, dd);
        ull ddp[KC];
#pragma unroll
        for (int b = 0; b < KC; b++) ddp[b] = pk2(dd[b], dd[b]);
        ull a2 = 0ull;
        unsigned waddr = wbase;
#pragma unroll
        for (int a = 0; a < KC; a++) {
            ull w = lds64(waddr); waddr += 8;
            ull h = f2mul(w, ddp[a]);
#pragma unroll
            for (int b = a + 1; b < KC; b++) {
                w = lds64(waddr); waddr += 8;
                h = f2fma(w, ddp[b], h);
            }
            a2 = f2fma(ddp[a], h, a2);
        }
        float n0, n1;
        upk2(a2, n0, n1);
        acc += (double)n0;
    }

    // ---------------- block reduction (double) -------------------------------
#pragma unroll
    for (int o = 16; o > 0; o >>= 1) acc += __shfl_down_sync(full, acc, o);
    if (lane == 0) sred[warp] = acc;
    __syncthreads();
    if (t == 0) {
        double v = 0.0;
#pragma unroll
        for (int w2 = 0; w2 < NTHREADS / 32; w2++) v += sred[w2];
        g_part[blockIdx.x] = v;
        __threadfence();
        unsigned old = atomicAdd(&g_ctr, 1u);
        s_last = (old == gridDim.x - 1) ? 1 : 0;
    }
    __syncthreads();

    // ---------------- last block finalizes -----------------------------------
    if (s_last && warp == 0) {
        double s = 0.0;
        for (int b = lane; b < GRID; b += 32) s += g_part[b];
#pragma unroll
        for (int o = 16; o > 0; o >>= 1) s += __shfl_down_sync(full, s, o);
        if (lane == 0) {
            out[0] = (float)(-(log(s) - (double)slogz) / (double)N);
            g_ctr = 0;   // reset for next graph replay
        }
    }
}

extern "C" void kernel_launch(void* const* d_in, const int* in_sizes, int n_in,
                              void* d_out, int out_size) {
    const float* X       = (const float*)d_in[0];
    const float* means   = (const float*)d_in[1];
    const float* chols   = (const float*)d_in[2];
    const float* weights = (const float*)d_in[3];
    const int N = in_sizes[0] / 4;
    float* out = (float*)d_out;

    gmm_all<<<GRID, NTHREADS>>>((const float4*)X, means, chols, weights, out, N);
}

// round 14
// speedup vs baseline: 1.1604x; 1.0743x over previous
#include <cuda_runtime.h>
#include <math.h>

#define KC 8
#define GRID 296
#define NTHREADS 128

typedef unsigned long long ull;

__device__ double g_part[GRID];
__device__ unsigned int g_ctr;   // zero-init; finalizer resets to 0 each run

// ---- packed f32x2 helpers ----
__device__ __forceinline__ ull f2fma(ull a, ull b, ull c) {
    ull r; asm("fma.rn.f32x2 %0, %1, %2, %3;" : "=l"(r) : "l"(a), "l"(b), "l"(c)); return r;
}
__device__ __forceinline__ ull f2mul(ull a, ull b) {
    ull r; asm("mul.rn.f32x2 %0, %1, %2;" : "=l"(r) : "l"(a), "l"(b)); return r;
}
__device__ __forceinline__ ull pk2(float lo, float hi) {
    ull r; asm("mov.b64 %0, {%1, %2};" : "=l"(r) : "f"(lo), "f"(hi)); return r;
}
__device__ __forceinline__ void upk2(ull v, float& lo, float& hi) {
    asm("mov.b64 {%0, %1}, %2;" : "=f"(lo), "=f"(hi) : "l"(v));
}
__device__ __forceinline__ float ex2f(float x) {
    float r; asm("ex2.approx.f32 %0, %1;" : "=f"(r) : "f"(x)); return r;
}

// density + W-quadratic for one point (cluster-paired density, scalar quad)
__device__ __forceinline__ float point_num(
    float4 x, const ull PA[4][10], const ull PB[4][4], const ull PC2[4],
    const float WP[36])
{
    ull Xx = pk2(x.x, x.x), Xy = pk2(x.y, x.y), Xz = pk2(x.z, x.z), Xw = pk2(x.w, x.w);
    const ull NEG1 = pk2(-1.0f, -1.0f);
    float d[KC];
#pragma unroll
    for (int p = 0; p < 4; p++) {
        ull y0 = f2fma(PA[p][0], Xx, PB[p][0]);
        ull y1 = f2fma(PA[p][1], Xx, f2fma(PA[p][2], Xy, PB[p][1]));
        ull y2 = f2fma(PA[p][3], Xx, f2fma(PA[p][4], Xy, f2fma(PA[p][5], Xz, PB[p][2])));
        ull y3 = f2fma(PA[p][6], Xx, f2fma(PA[p][7], Xy, f2fma(PA[p][8], Xz, f2fma(PA[p][9], Xw, PB[p][3]))));
        ull s = f2mul(y0, y0);
        s = f2fma(y1, y1, s);
        s = f2fma(y2, y2, s);
        s = f2fma(y3, y3, s);
        ull tq = f2fma(s, NEG1, PC2[p]);   // C2 - s, packed
        float t0, t1;
        upk2(tq, t0, t1);
        d[2 * p]     = ex2f(t0);
        d[2 * p + 1] = ex2f(t1);
    }
    // scalar symmetric quad; dual accumulators shorten the tail chain
    float numA = 0.0f, numB = 0.0f;
    int idx = 0;
#pragma unroll
    for (int a = 0; a < KC; a++) {
        float h = WP[idx++] * d[a];
#pragma unroll
        for (int b = a + 1; b < KC; b++) h = fmaf(WP[idx++], d[b], h);
        if (a & 1) numB = fmaf(d[a], h, numB);
        else       numA = fmaf(d[a], h, numA);
    }
    return numA + numB;
}

// =======================================================================
// ONE fused kernel: per-block redundant setup -> main loop (uniform trip
// count, 4-pt unroll, software-pipelined loads) -> balanced strided tail
// -> last-block finalize.
// =======================================================================
__global__ void __launch_bounds__(NTHREADS) gmm_all(
    const float4* __restrict__ X,
    const float*  __restrict__ means,
    const float*  __restrict__ chols,
    const float*  __restrict__ weights,
    float* __restrict__ out, int N)
{
    __shared__ float sA[KC][10];
    __shared__ float sB[KC][4];
    __shared__ float sC2[KC];
    __shared__ float sW[KC][KC];
    __shared__ float sSig[KC][16];
    __shared__ float red0[2], red1[2], red2[2];
    __shared__ float slogz;
    __shared__ double sred[NTHREADS / 32];
    __shared__ int s_last;

    const int t = threadIdx.x;
    const int lane = t & 31, warp = t >> 5;
    const unsigned full = 0xffffffffu;
    const float LOG2E = 1.4426950408889634f;
    const float LN2PI = 1.8378770664093454f;
    const float SCL   = 0.8493218002880191f;   // sqrt(0.5*log2(e))

    // ---------------- setup phase 1: per-cluster constants (threads 0..7) ----
    if (t < KC) {
        const int k = t;
        float L[4][4];
#pragma unroll
        for (int r = 0; r < 4; r++)
#pragma unroll
            for (int c = 0; c < 4; c++)
                L[r][c] = (c <= r) ? chols[k * 16 + r * 4 + c] : 0.0f;
        float S[4][4];
#pragma unroll
        for (int r = 0; r < 4; r++)
#pragma unroll
            for (int c = 0; c < 4; c++) {
                float s = (r == c) ? 1.0f : 0.0f;
#pragma unroll
                for (int m = 0; m < 4; m++) s = fmaf(L[r][m], L[c][m], s);
                S[r][c] = s;
                sSig[k][r * 4 + c] = s;
            }
        float M[4][4];
#pragma unroll
        for (int r = 0; r < 4; r++) {
#pragma unroll
            for (int c = 0; c < 4; c++) {
                if (c > r) { M[r][c] = 0.0f; continue; }
                float s = S[r][c];
#pragma unroll
                for (int m = 0; m < 4; m++)
                    if (m < c) s = fmaf(-M[r][m], M[c][m], s);
                if (r == c) M[r][r] = sqrtf(s);
                else        M[r][c] = s / M[c][c];
            }
        }
        float A[4][4];
#pragma unroll
        for (int r = 0; r < 4; r++) {
#pragma unroll
            for (int c = 0; c < 4; c++) A[r][c] = 0.0f;
            A[r][r] = 1.0f / M[r][r];
#pragma unroll
            for (int c = 0; c < 4; c++) {
                if (c >= r) continue;
                float s = 0.0f;
#pragma unroll
                for (int m = 0; m < 4; m++)
                    if (m >= c && m < r) s = fmaf(M[r][m], A[m][c], s);
                A[r][c] = -s * A[r][r];
            }
        }
        float logdet = 2.0f * logf(M[0][0] * M[1][1] * M[2][2] * M[3][3]);
        sC2[k] = -0.5f * (4.0f * LN2PI + logdet) * LOG2E;
        int idx = 0;
#pragma unroll
        for (int r = 0; r < 4; r++)
#pragma unroll
            for (int c = 0; c < 4; c++)
                if (c <= r) sA[k][idx++] = A[r][c] * SCL;
#pragma unroll
        for (int r = 0; r < 4; r++) {
            float b = 0.0f;
#pragma unroll
            for (int c = 0; c < 4; c++)
                if (c <= r) b = fmaf(A[r][c], means[k * 4 + c], b);
            sB[k][r] = -b * SCL;
        }
    }
    __syncthreads();

    // ---------------- setup phase 2: softmax W + z (threads 0..63) ----------
    const int i8 = t >> 3, j8 = t & 7;
    float wij = 0.0f, m = -1e30f;
    if (t < 64) {
        wij = weights[i8] * weights[j8];
        m = wij;
#pragma unroll
        for (int o = 16; o > 0; o >>= 1) m = fmaxf(m, __shfl_xor_sync(full, m, o));
        if (lane == 0) red0[warp] = m;
    }
    __syncthreads();
    float e = 0.0f;
    if (t < 64) {
        m = fmaxf(red0[0], red0[1]);
        e = __expf(wij - m);
        float s = e;
#pragma unroll
        for (int o = 16; o > 0; o >>= 1) s += __shfl_xor_sync(full, s, o);
        if (lane == 0) red1[warp] = s;
    }
    __syncthreads();
    if (t < 64) {
        float s = red1[0] + red1[1];
        float Wij = e / s;
        sW[i8][j8] = Wij;
        float Ss[4][4];
#pragma unroll
        for (int r = 0; r < 4; r++)
#pragma unroll
            for (int c = 0; c < 4; c++)
                Ss[r][c] = sSig[i8][r * 4 + c] + sSig[j8][r * 4 + c];
        float M[4][4];
#pragma unroll
        for (int r = 0; r < 4; r++) {
#pragma unroll
            for (int c = 0; c < 4; c++) {
                if (c > r) { M[r][c] = 0.0f; continue; }
                float s2 = Ss[r][c];
#pragma unroll
                for (int mm = 0; mm < 4; mm++)
                    if (mm < c) s2 = fmaf(-M[r][mm], M[c][mm], s2);
                if (r == c) M[r][r] = sqrtf(s2);
                else        M[r][c] = s2 / M[c][c];
            }
        }
        float ld = 2.0f * logf(M[0][0] * M[1][1] * M[2][2] * M[3][3]);
        float y[4];
#pragma unroll
        for (int r = 0; r < 4; r++) {
            float s2 = means[i8 * 4 + r] - means[j8 * 4 + r];
#pragma unroll
            for (int mm = 0; mm < 4; mm++)
                if (mm < r) s2 = fmaf(-M[r][mm], y[mm], s2);
            y[r] = s2 / M[r][r];
        }
        float md = y[0] * y[0] + y[1] * y[1] + y[2] * y[2] + y[3] * y[3];
        float zc = Wij * __expf(-0.5f * md - 0.5f * (4.0f * LN2PI + ld));
#pragma unroll
        for (int o = 16; o > 0; o >>= 1) zc += __shfl_xor_sync(full, zc, o);
        if (lane == 0) red2[warp] = zc;
    }
    __syncthreads();
    if (t == 0) slogz = logf(red2[0] + red2[1]);
    __syncthreads();

    // ---------------- load + pack constants into registers -------------------
    ull PA[4][10], PB[4][4], PC2[4];
    float WP[36];
#pragma unroll
    for (int p = 0; p < 4; p++) {
#pragma unroll
        for (int q = 0; q < 10; q++) PA[p][q] = pk2(sA[2 * p][q], sA[2 * p + 1][q]);
#pragma unroll
        for (int q = 0; q < 4; q++)  PB[p][q] = pk2(sB[2 * p][q], sB[2 * p + 1][q]);
        PC2[p] = pk2(sC2[2 * p], sC2[2 * p + 1]);
    }
    {
        int idx = 0;
#pragma unroll
        for (int a = 0; a < KC; a++) {
            WP[idx++] = sW[a][a];
#pragma unroll
            for (int b = a + 1; b < KC; b++) WP[idx++] = 2.0f * sW[a][b];
        }
    }

    // ---------------- main loop: uniform trip count, pipelined ---------------
    // Every thread executes exactly Kiter 4-pt groups (perfect balance);
    // the remaining N - Kiter*step points go 1/thread in a strided tail.
    double acc = 0.0;
    const int gid = blockIdx.x * blockDim.x + t;
    const int nthr = gridDim.x * blockDim.x;
    const int step = 4 * nthr;
    const int Kiter = N / step;
    int i = 4 * gid;

    if (Kiter > 0) {
        float4 xa = X[i];
        float4 xb = X[i + 1];
        float4 xc = X[i + 2];
        float4 xd = X[i + 3];
        for (int r = 0; r < Kiter; r++) {
            const int inext = i + step;
            float4 ya, yb, yc, yd;
            if (r + 1 < Kiter) {       // prefetch next group BEFORE computing
                ya = X[inext];
                yb = X[inext + 1];
                yc = X[inext + 2];
                yd = X[inext + 3];
            }
            float n0 = point_num(xa, PA, PB, PC2, WP);
            float n1 = point_num(xb, PA, PB, PC2, WP);
            float n2 = point_num(xc, PA, PB, PC2, WP);
            float n3 = point_num(xd, PA, PB, PC2, WP);
            acc += (double)((n0 + n1) + (n2 + n3));
            xa = ya; xb = yb; xc = yc; xd = yd;
            i = inext;
        }
    }
    // balanced tail: N - Kiter*step points, at most 1 per thread
    for (int j = Kiter * step + gid; j < N; j += nthr)
        acc += (double)point_num(X[j], PA, PB, PC2, WP);

    // ---------------- block reduction (double) -------------------------------
#pragma unroll
    for (int o = 16; o > 0; o >>= 1) acc += __shfl_down_sync(full, acc, o);
    if (lane == 0) sred[warp] = acc;
    __syncthreads();
    if (t == 0) {
        double v = 0.0;
#pragma unroll
        for (int w2 = 0; w2 < NTHREADS / 32; w2++) v += sred[w2];
        g_part[blockIdx.x] = v;
        __threadfence();
        unsigned old = atomicAdd(&g_ctr, 1u);
        s_last = (old == gridDim.x - 1) ? 1 : 0;
    }
    __syncthreads();

    // ---------------- last block finalizes -----------------------------------
    if (s_last && warp == 0) {
        double s = 0.0;
        for (int b = lane; b < GRID; b += 32) s += g_part[b];
#pragma unroll
        for (int o = 16; o > 0; o >>= 1) s += __shfl_down_sync(full, s, o);
        if (lane == 0) {
            out[0] = (float)(-(log(s) - (double)slogz) / (double)N);
            g_ctr = 0;   // reset for next graph replay
        }
    }
}

extern "C" void kernel_launch(void* const* d_in, const int* in_sizes, int n_in,
                              void* d_out, int out_size) {
    const float* X       = (const float*)d_in[0];
    const float* means   = (const float*)d_in[1];
    const float* chols   = (const float*)d_in[2];
    const float* weights = (const float*)d_in[3];
    const int N = in_sizes[0] / 4;
    float* out = (float*)d_out;

    gmm_all<<<GRID, NTHREADS>>>((const float4*)X, means, chols, weights, out, N);
}